// round 6
// baseline (speedup 1.0000x reference)
#include <cuda_runtime.h>
#include <cstdint>
#include <cstddef>

#define VOCAB 100000
#define EMBED 64
#define SENT  20
#define MEM   50
#define BATCH 32
#define HOPS  3

// ---------------- scratch (static device globals; no allocations) ------------
__device__ float g_S[4][BATCH][MEM][EMBED];     // encoding-weighted sums, 1.6 MB
__device__ float g_u[BATCH * EMBED];            // u state [b][e]
__device__ float g_uT[EMBED * BATCH];           // u transposed [e][b] for GEMM

// ---------------- packed f32x2 helpers (sm_100+) -----------------------------
__device__ __forceinline__ unsigned long long pack2(float lo, float hi) {
    unsigned long long r;
    asm("mov.b64 %0, {%1, %2};" : "=l"(r) : "f"(lo), "f"(hi));
    return r;
}
__device__ __forceinline__ void unpack2(unsigned long long v, float& lo, float& hi) {
    asm("mov.b64 {%0, %1}, %2;" : "=f"(lo), "=f"(hi) : "l"(v));
}
#define FMA2(d, a, b) asm("fma.rn.f32x2 %0, %1, %2, %3;" : "=l"(d) : "l"(a), "l"(b), "l"(d))

// ---------------- kernel 1: gather + position-encoded sums -------------------
// ONE WARP PER TASK (lane = float2 slice of E). 6432 tasks = 804 blocks x 8
// warps -> ~44 warps/SM. Indices live in registers + shfl. All 20 row-gathers
// are batched into a register array BEFORE the FMA loop (MLP=20) so each warp
// pays ~one DRAM latency, not five.
__global__ void __launch_bounds__(256) k_embed_sums(
    const int* __restrict__ stories, const int* __restrict__ queries,
    const float* __restrict__ A, const float* __restrict__ C,
    const float* __restrict__ enc)
{
    __shared__ __align__(8) float2 enc2[SENT * 32];   // enc[s][2l..2l+1]
    const int tid  = threadIdx.x;
    const int lane = tid & 31;
    const int task = blockIdx.x * 8 + (tid >> 5);     // 0..6431

    for (int i = tid; i < SENT * 32; i += 256)
        enc2[i] = __ldg(((const float2*)enc) + i);

    const int*   src;
    const float* tab;
    float*       dst;
    if (task < 4 * BATCH * MEM) {
        const int t   = task / (BATCH * MEM);
        const int rem = task % (BATCH * MEM);         // b*MEM + m
        src = stories + rem * SENT;
        tab = (t == 0) ? A : (C + (size_t)(t - 1) * VOCAB * EMBED);
        dst = &g_S[t][0][0][0] + (size_t)rem * EMBED;
    } else {
        const int b = task - 4 * BATCH * MEM;         // 0..31
        src = queries + b * SENT;
        tab = A;
        dst = g_u + b * EMBED;
    }

    int idx_reg = 0;
    if (lane < SENT) idx_reg = __ldg(src + lane);
    __syncthreads();   // enc2 ready

    // batch all 20 gathers (independent -> high MLP)
    float2 w[SENT];
    #pragma unroll
    for (int s = 0; s < SENT; ++s) {
        const int idx = __shfl_sync(0xffffffffu, idx_reg, s);
        w[s] = __ldg((const float2*)(tab + (size_t)idx * EMBED) + lane);
    }
    float2 acc = make_float2(0.f, 0.f);
    #pragma unroll
    for (int s = 0; s < SENT; ++s) {
        const float2 en = enc2[s * 32 + lane];
        acc.x = fmaf(w[s].x, en.x, acc.x);
        acc.y = fmaf(w[s].y, en.y, acc.y);
    }
    ((float2*)dst)[lane] = acc;
}

// ---------------- kernel 2: the 3 attention hops -----------------------------
// One block per batch. All four S[.][b] tiles cached in shared (pitch 65),
// warp-parallel softmax, 4-thread-per-m dots.
#define SP 65
__global__ void __launch_bounds__(256) k_hops()
{
    const int b   = blockIdx.x;
    const int tid = threadIdx.x;
    __shared__ float S_sh[4 * MEM * SP];   // 52 KB
    __shared__ float u_sh[EMBED];
    __shared__ float d_sh[MEM];

    #pragma unroll
    for (int t = 0; t < 4; ++t) {
        const float4* src = (const float4*)(&g_S[t][b][0][0]);
        float* dstp = S_sh + t * MEM * SP;
        for (int i = tid; i < MEM * 16; i += 256) {
            const float4 v = src[i];
            const int m = i >> 4, e0 = (i & 15) * 4;
            float* p = dstp + m * SP + e0;
            p[0] = v.x; p[1] = v.y; p[2] = v.z; p[3] = v.w;
        }
    }
    if (tid < EMBED) u_sh[tid] = g_u[b * EMBED + tid];
    __syncthreads();

    #pragma unroll
    for (int hop = 0; hop < HOPS; ++hop) {
        {
            const int m = tid >> 2, q = tid & 3;
            const float* Sm = S_sh + hop * MEM * SP + m * SP;
            float d = 0.f;
            #pragma unroll
            for (int k = 0; k < 16; ++k) {
                const int e = q + 4 * k;
                d = fmaf(Sm[e], u_sh[e], d);
            }
            d += __shfl_xor_sync(0xffffffffu, d, 1);
            d += __shfl_xor_sync(0xffffffffu, d, 2);
            if (q == 0 && m < MEM) d_sh[m] = d;
        }
        __syncthreads();
        if (tid < 32) {
            const float v1 = d_sh[tid];
            const float v2 = (tid < MEM - 32) ? d_sh[tid + 32] : -3.4e38f;
            float mx = fmaxf(v1, v2);
            #pragma unroll
            for (int off = 16; off; off >>= 1)
                mx = fmaxf(mx, __shfl_xor_sync(0xffffffffu, mx, off));
            const float e1 = __expf(v1 - mx);
            const float e2 = (tid < MEM - 32) ? __expf(v2 - mx) : 0.f;
            float s = e1 + e2;
            #pragma unroll
            for (int off = 16; off; off >>= 1)
                s += __shfl_xor_sync(0xffffffffu, s, off);
            const float inv = 1.f / s;
            d_sh[tid] = e1 * inv;
            if (tid < MEM - 32) d_sh[tid + 32] = e2 * inv;
        }
        __syncthreads();
        if (tid < EMBED) {
            const float* Sc = S_sh + (hop + 1) * MEM * SP + tid;
            float o = 0.f;
            #pragma unroll
            for (int m = 0; m < MEM; ++m)
                o = fmaf(d_sh[m], Sc[m * SP], o);
            u_sh[tid] += o;
        }
        __syncthreads();
    }

    if (tid < EMBED) {
        const float u = u_sh[tid];
        g_u[b * EMBED + tid] = u;
        g_uT[tid * BATCH + b] = u;
    }
}

// ---------------- kernel 3: vocab projection  out = u @ C2^T -----------------
// 64 threads/block, 128 vocab rows/block. C2 tile staged TRANSPOSED [e][row]
// with pitch 129: C reads become lane-consecutive conflict-free LDS.32 (2/e),
// u-pairs are broadcast LDS.128 (8/e) -> 640 LDS vs 2048 packed FMA2 per
// thread; the FMA pipe is the binding constraint.
#define GT 64
#define TILE_V 128
#define TP 129   // transposed tile pitch (floats)
__global__ void __launch_bounds__(GT) k_vocab_gemm(
    const float* __restrict__ C2, float* __restrict__ out)
{
    __shared__ float tileT[EMBED * TP];                 // 33 KB, [e][row]
    __shared__ __align__(16) float us[EMBED * BATCH];   // [e][b], 8 KB
    const int tid = threadIdx.x;
    const long gbase = (long)blockIdx.x * TILE_V;

    #pragma unroll
    for (int i = 0; i < (EMBED * BATCH / 4) / GT; ++i)
        ((float4*)us)[tid + i * GT] = __ldg(((const float4*)g_uT) + tid + i * GT);

    // coalesced float4 global load, transposed scatter to shared
    for (int i = tid; i < TILE_V * 16; i += GT) {
        const int row = i >> 4, c = i & 15;
        float4 v = make_float4(0.f, 0.f, 0.f, 0.f);
        if (gbase + row < VOCAB)
            v = __ldg((const float4*)(C2 + (gbase + row) * EMBED) + c);
        tileT[(4 * c + 0) * TP + row] = v.x;
        tileT[(4 * c + 1) * TP + row] = v.y;
        tileT[(4 * c + 2) * TP + row] = v.z;
        tileT[(4 * c + 3) * TP + row] = v.w;
    }
    __syncthreads();

    unsigned long long acc0[16], acc1[16];
    #pragma unroll
    for (int j = 0; j < 16; ++j) { acc0[j] = 0ull; acc1[j] = 0ull; }

    #pragma unroll 8
    for (int e = 0; e < EMBED; ++e) {
        const float cA = tileT[e * TP + tid];        // row tid
        const float cB = tileT[e * TP + GT + tid];   // row tid+64
        const unsigned long long a2 = pack2(cA, cA);
        const unsigned long long b2 = pack2(cB, cB);
        const ulonglong2* up = (const ulonglong2*)(us + e * BATCH);
        #pragma unroll
        for (int j = 0; j < 8; ++j) {
            const ulonglong2 uu = up[j];   // batches 4j..4j+3 (paired)
            FMA2(acc0[2 * j],     a2, uu.x);
            FMA2(acc0[2 * j + 1], a2, uu.y);
            FMA2(acc1[2 * j],     b2, uu.x);
            FMA2(acc1[2 * j + 1], b2, uu.y);
        }
    }

    const long vA = gbase + tid;
    const long vB = gbase + GT + tid;
    #pragma unroll
    for (int j = 0; j < 16; ++j) {
        float lo0, hi0, lo1, hi1;
        unpack2(acc0[j], lo0, hi0);
        unpack2(acc1[j], lo1, hi1);
        const long b0 = 2 * j, b1 = 2 * j + 1;
        if (vA < VOCAB) { out[b0 * VOCAB + vA] = lo0; out[b1 * VOCAB + vA] = hi0; }
        if (vB < VOCAB) { out[b0 * VOCAB + vB] = lo1; out[b1 * VOCAB + vB] = hi1; }
    }
}

// ---------------- launch -----------------------------------------------------
extern "C" void kernel_launch(void* const* d_in, const int* in_sizes, int n_in,
                              void* d_out, int out_size)
{
    const int* stories = nullptr;
    const int* queries = nullptr;
    const float* A = nullptr;
    const float* C = nullptr;
    const float* enc = nullptr;
    for (int i = 0; i < n_in; ++i) {
        switch (in_sizes[i]) {
            case BATCH * MEM * SENT:   stories = (const int*)d_in[i];   break;
            case BATCH * SENT:         queries = (const int*)d_in[i];   break;
            case VOCAB * EMBED:        A       = (const float*)d_in[i]; break;
            case HOPS * VOCAB * EMBED: C       = (const float*)d_in[i]; break;
            case SENT * EMBED:         enc     = (const float*)d_in[i]; break;
            default: break;
        }
    }
    float* out = (float*)d_out;
    const float* C2 = C + (size_t)(HOPS - 1) * VOCAB * EMBED;

    k_embed_sums<<<(4 * BATCH * MEM + BATCH) / 8, 256>>>(stories, queries, A, C, enc);
    k_hops<<<BATCH, 256>>>();
    k_vocab_gemm<<<(VOCAB + TILE_V - 1) / TILE_V, GT>>>(C2, out);
    (void)out_size;
}